// round 13
// baseline (speedup 1.0000x reference)
#include <cuda_runtime.h>
#include <cstdint>
#include <math.h>

// Problem constants (fixed by setup_inputs)
#define WINC    20
#define OFFSETC 40
#define FDIM    8192
#define CDIM    256
#define PDIM    256
#define SIL_BLOCKS 1024        // B * 32 chunks of 256 frames
#define PH_BLOCKS  1024        // B*P / 8 warps
#define NBLK    (SIL_BLOCKS + PH_BLOCKS)
#define NTHR    256

// Gaussian taps g[i] = exp(-0.5*((i-4)/4)^2) / sum, precomputed to float32
// accuracy (matches the jnp float32 computation to ~1e-7 relative).
#define G0 0.08167445f
#define G1 0.10164549f
#define G2 0.11883562f
#define G3 0.13051539f
#define G4 0.13465840f

__device__ float        g_acc    = 0.0f;   // self-resetting accumulator
__device__ unsigned int g_ticket = 0;      // self-resetting arrival counter

__device__ __forceinline__ float block_reduce_sum(float v) {
    __shared__ float sh[8];
    int lane = threadIdx.x & 31;
    int w    = threadIdx.x >> 5;
    #pragma unroll
    for (int o = 16; o; o >>= 1) v += __shfl_down_sync(0xffffffffu, v, o);
    if (lane == 0) sh[w] = v;
    __syncthreads();
    if (w == 0) {
        v = (lane < 8) ? sh[lane] : 0.0f;
        #pragma unroll
        for (int o = 4; o; o >>= 1) v += __shfl_down_sync(0xffffffffu, v, o);
    }
    return v;
}

// 2048 blocks x 256 threads (best measured gather geometry, R11: 8.2us).
//  blocks [0, SIL_BLOCKS): silence, 256 frames each (b = bid>>5, ch = bid&31)
//  blocks [SIL_BLOCKS, NBLK): phonemes, one per warp (8 per block)
// Finalize: each block REDG-adds its partial into g_acc, then bumps an
// acq_rel ticket; the last arriver publishes out[0] = atomicExch(g_acc, 0)
// and resets the ticket — no memset node, single graph node.
__global__ void __launch_bounds__(NTHR)
fused_kernel(const float* __restrict__ X,
             const int* __restrict__ lengths,
             const int* __restrict__ tgt,
             const int* __restrict__ p_end,
             const int* __restrict__ pnum,
             float* __restrict__ out) {
    const unsigned FULL = 0xffffffffu;
    int bid  = blockIdx.x;
    int tid  = threadIdx.x;
    int lane = tid & 31;
    int wid  = tid >> 5;

    float contrib = 0.0f;

    if (bid < SIL_BLOCKS) {
        // ---------- silence term: one frame per thread ----------
        int b  = bid >> 5;                 // 32 chunks per batch
        int ch = bid & 31;
        int tf = (ch << 8) + tid;

        int len = __ldg(&lengths[b]);
        int pn  = __ldg(&pnum[b]);
        int ends_ph = min(__ldg(&p_end[b]) + OFFSETC, len);
        int first_start = max(ends_ph - WINC * pn, 0);
        int last_end    = min(max(ends_ph - WINC, 0) + WINC, len);

        // mask = (tf < first_start) | ((tf >= last_end) & (tf < len))
        if ((tf < first_start) || ((tf >= last_end) && (tf < len))) {
            contrib = -X[((size_t)b * FDIM + tf) * CDIM];   // SIL column = 0
        }
    } else {
        // ---------- phoneme term: one (b, p) per warp ----------
        int w = ((bid - SIL_BLOCKS) << 3) + wid;   // global warp id in [0, B*P)
        int b = w >> 8;                            // P = 256
        int p = w & 255;

        int len = __ldg(&lengths[b]);
        int pn  = __ldg(&pnum[b]);

        if (p < pn) {
            int ends_ph = min(__ldg(&p_end[b]) + OFFSETC, len);
            int start   = max(ends_ph - WINC * (pn - p), 0);
            int wlen    = min(start + WINC, len) - start;
            int c       = __ldg(&tgt[b * PDIM + p]);

            float v = 0.0f;
            if (lane < WINC && lane < wlen) {
                int fi = min(start + lane, FDIM - 1);
                v = X[((size_t)b * FDIM + fi) * CDIM + c];
            }

            // smoothed[lane] = sum_i g[i] * v[lane + i - 3]; out-of-range -> 0
            // (idx & 31 wraps onto lanes >= 20 which hold v = 0)
            float v0 = __shfl_sync(FULL, v, (lane - 3) & 31);
            float v1 = __shfl_sync(FULL, v, (lane - 2) & 31);
            float v2 = __shfl_sync(FULL, v, (lane - 1) & 31);
            float v4 = __shfl_sync(FULL, v, (lane + 1) & 31);
            float v5 = __shfl_sync(FULL, v, (lane + 2) & 31);
            float v6 = __shfl_sync(FULL, v, (lane + 3) & 31);
            float v7 = __shfl_sync(FULL, v, (lane + 4) & 31);
            float v8 = __shfl_sync(FULL, v, (lane + 5) & 31);
            float sm = G0 * v0;
            sm = fmaf(G1, v1, sm);
            sm = fmaf(G2, v2, sm);
            sm = fmaf(G3, v,  sm);
            sm = fmaf(G4, v4, sm);
            sm = fmaf(G3, v5, sm);
            sm = fmaf(G2, v6, sm);
            sm = fmaf(G1, v7, sm);
            sm = fmaf(G0, v8, sm);

            float m = (lane < wlen && lane < WINC) ? sm : -INFINITY;
            #pragma unroll
            for (int o = 16; o; o >>= 1) m = fmaxf(m, __shfl_xor_sync(FULL, m, o));
            if (lane == 0) contrib = -m;
        }
    }

    float tot = block_reduce_sum(contrib);

    if (tid == 0) {
        atomicAdd(&g_acc, tot);            // REDG into device accumulator
        unsigned int t;
        // release: orders our g_acc add before the ticket increment;
        // acquire: the last arriver sees every released g_acc add.
        asm volatile("atom.add.acq_rel.gpu.global.u32 %0, [%1], %2;"
                     : "=r"(t) : "l"(&g_ticket), "r"(1u) : "memory");
        if (t == (unsigned int)(NBLK - 1)) {
            // read the total AND re-zero for the next graph replay
            out[0] = atomicExch(&g_acc, 0.0f);
            g_ticket = 0;
        }
    }
}

extern "C" void kernel_launch(void* const* d_in, const int* in_sizes, int n_in,
                              void* d_out, int out_size) {
    const float* X       = (const float*)d_in[0];
    const int*   lengths = (const int*)d_in[1];
    const int*   tgt     = (const int*)d_in[2];
    const int*   p_end   = (const int*)d_in[3];
    const int*   pnum    = (const int*)d_in[4];
    float*       out     = (float*)d_out;

    fused_kernel<<<NBLK, NTHR>>>(X, lengths, tgt, p_end, pnum, out);
}

// round 14
// speedup vs baseline: 1.0467x; 1.0467x over previous
#include <cuda_runtime.h>
#include <cstdint>
#include <math.h>

// Problem constants (fixed by setup_inputs)
#define WINC    20
#define OFFSETC 40
#define FDIM    8192
#define CDIM    256
#define PDIM    256
#define SIL_BLOCKS 128         // 2048 frames per block: 8 per thread, front-batched
#define PH_BLOCKS  1024        // B*P / 8 warps, one phoneme per warp (R11 best)
#define NBLK    (SIL_BLOCKS + PH_BLOCKS)   // 1152 < 1184 -> single wave
#define NTHR    256

// Gaussian taps g[i] = exp(-0.5*((i-4)/4)^2) / sum, precomputed to float32
// accuracy (matches the jnp float32 computation to ~1e-7 relative).
#define G0 0.08167445f
#define G1 0.10164549f
#define G2 0.11883562f
#define G3 0.13051539f
#define G4 0.13465840f

__device__ __forceinline__ float block_reduce_sum(float v) {
    __shared__ float sh[8];
    int lane = threadIdx.x & 31;
    int w    = threadIdx.x >> 5;
    #pragma unroll
    for (int o = 16; o; o >>= 1) v += __shfl_down_sync(0xffffffffu, v, o);
    if (lane == 0) sh[w] = v;
    __syncthreads();
    if (w == 0) {
        v = (lane < 8) ? sh[lane] : 0.0f;
        #pragma unroll
        for (int o = 4; o; o >>= 1) v += __shfl_down_sync(0xffffffffu, v, o);
    }
    return v;
}

// Single-wave kernel: 1152 blocks x 256 threads.
//  blocks [0, PH_BLOCKS): phonemes, one per warp (8 per block) — R11 geometry.
//  blocks [PH_BLOCKS, NBLK): silence, 2048 frames each, 8 per thread with all
//  8 predicated LDGs front-batched (MLP=8 -> one latency exposure, not eight).
// Block partial -> RED.ADD.F32 into out[0] (all terms >= 0; reorder ~1e-7).
__global__ void __launch_bounds__(NTHR)
fused_kernel(const float* __restrict__ X,
             const int* __restrict__ lengths,
             const int* __restrict__ tgt,
             const int* __restrict__ p_end,
             const int* __restrict__ pnum,
             float* __restrict__ out) {
    const unsigned FULL = 0xffffffffu;
    int bid  = blockIdx.x;
    int tid  = threadIdx.x;
    int lane = tid & 31;
    int wid  = tid >> 5;

    float contrib = 0.0f;

    if (bid < PH_BLOCKS) {
        // ---------- phoneme term: one (b, p) per warp ----------
        int w = (bid << 3) + wid;                  // global warp id in [0, B*P)
        int b = w >> 8;                            // P = 256
        int p = w & 255;

        int len = __ldg(&lengths[b]);
        int pn  = __ldg(&pnum[b]);

        if (p < pn) {
            int ends_ph = min(__ldg(&p_end[b]) + OFFSETC, len);
            int start   = max(ends_ph - WINC * (pn - p), 0);
            int wlen    = min(start + WINC, len) - start;
            int c       = __ldg(&tgt[b * PDIM + p]);

            float v = 0.0f;
            if (lane < WINC && lane < wlen) {
                int fi = min(start + lane, FDIM - 1);
                v = X[((size_t)b * FDIM + fi) * CDIM + c];
            }

            // smoothed[lane] = sum_i g[i] * v[lane + i - 3]; out-of-range -> 0
            // (idx & 31 wraps onto lanes >= 20 which hold v = 0)
            float v0 = __shfl_sync(FULL, v, (lane - 3) & 31);
            float v1 = __shfl_sync(FULL, v, (lane - 2) & 31);
            float v2 = __shfl_sync(FULL, v, (lane - 1) & 31);
            float v4 = __shfl_sync(FULL, v, (lane + 1) & 31);
            float v5 = __shfl_sync(FULL, v, (lane + 2) & 31);
            float v6 = __shfl_sync(FULL, v, (lane + 3) & 31);
            float v7 = __shfl_sync(FULL, v, (lane + 4) & 31);
            float v8 = __shfl_sync(FULL, v, (lane + 5) & 31);
            float sm = G0 * v0;
            sm = fmaf(G1, v1, sm);
            sm = fmaf(G2, v2, sm);
            sm = fmaf(G3, v,  sm);
            sm = fmaf(G4, v4, sm);
            sm = fmaf(G3, v5, sm);
            sm = fmaf(G2, v6, sm);
            sm = fmaf(G1, v7, sm);
            sm = fmaf(G0, v8, sm);

            float m = (lane < wlen && lane < WINC) ? sm : -INFINITY;
            #pragma unroll
            for (int o = 16; o; o >>= 1) m = fmaxf(m, __shfl_xor_sync(FULL, m, o));
            if (lane == 0) contrib = -m;
        }
    } else {
        // ---------- silence term: 8 front-batched frames per thread ----------
        int sb = bid - PH_BLOCKS;          // [0, 128)
        int b  = sb >> 2;                  // 4 chunks of 2048 frames per batch
        int ch = sb & 3;

        int len = __ldg(&lengths[b]);
        int pn  = __ldg(&pnum[b]);
        int ends_ph = min(__ldg(&p_end[b]) + OFFSETC, len);
        int first_start = max(ends_ph - WINC * pn, 0);
        int last_end    = min(max(ends_ph - WINC, 0) + WINC, len);
        const float* xp = X + (size_t)b * FDIM * CDIM;

        int tf0 = (ch << 11) + tid;        // frames tf0 + k*256, k = 0..7
        float acc[8];
        #pragma unroll
        for (int k = 0; k < 8; k++) {
            int tf = tf0 + (k << 8);
            // mask = (tf < first_start) | ((tf >= last_end) & (tf < len))
            bool m = (tf < first_start) || ((tf >= last_end) && (tf < len));
            acc[k] = m ? xp[(size_t)tf * CDIM] : 0.0f;   // SIL column = 0
        }
        float s = 0.0f;
        #pragma unroll
        for (int k = 0; k < 8; k++) s += acc[k];
        contrib = -s;
    }

    float tot = block_reduce_sum(contrib);
    if (tid == 0) atomicAdd(out, tot);     // RED.ADD.F32, no-return fast path
}

extern "C" void kernel_launch(void* const* d_in, const int* in_sizes, int n_in,
                              void* d_out, int out_size) {
    const float* X       = (const float*)d_in[0];
    const int*   lengths = (const int*)d_in[1];
    const int*   tgt     = (const int*)d_in[2];
    const int*   p_end   = (const int*)d_in[3];
    const int*   pnum    = (const int*)d_in[4];
    float*       out     = (float*)d_out;

    cudaMemsetAsync(out, 0, sizeof(float));          // graph-capturable memset node
    fused_kernel<<<NBLK, NTHR>>>(X, lengths, tgt, p_end, pnum, out);
}